// round 11
// baseline (speedup 1.0000x reference)
#include <cuda_runtime.h>
#include <cstdint>

// DeepInsightEncoding: out[b,h,w,c], c in {stamp, scatter, rowcopy, nd, bars}
// B=512, D=32, H=W=128. Output fp32 [512,128,128,5] = 168 MB -> HBM-write bound.
//
// R11: TMA bulk-store drain (R10) + scatter patched directly into the staging
// row (no di map, no di zeroing, no block scatter, one __syncthreads only).

#define THREADS 512            // 16 warps, one output row per warp
#define NWARPS 16
#define ROWS_PER_CTA 16
#define ROW_F4 160             // 128 px * 5 ch / 4 = 160 float4 = 2560 B per row

__global__ void __launch_bounds__(THREADS)
deepinsight_kernel(const float* __restrict__ inputs,   // [512,32]
                   const float* __restrict__ stamp,    // [128,128]
                   const int*   __restrict__ coords,   // [32,2]
                   float*       __restrict__ out)      // [512,128,128,5]
{
    __shared__ __align__(16) float4 stage[NWARPS][ROW_F4]; // 40 KB
    __shared__ float  sx[32];
    __shared__ int    sbarh[32];
    __shared__ char4  sc2b[32];
    __shared__ int    srow[32], scol[32];
    __shared__ float  s_inv_range;

    const int b    = blockIdx.x >> 3;
    const int h0   = (blockIdx.x & 7) * ROWS_PER_CTA;
    const int tid  = threadIdx.x;
    const int warp = tid >> 5;
    const int lane = tid & 31;

    // ---- prologue (warp 0 only) ----
    if (tid < 32) {
        float v = inputs[b * 32 + tid];
        sx[tid] = v;
        int bh = (int)rintf(v * 128.0f);          // round-half-even == jnp.round
        sbarh[tid] = min(max(bh, 0), 128);

        srow[tid] = coords[2 * tid];
        scol[tid] = coords[2 * tid + 1];

        float mn = v, mx = v;
        #pragma unroll
        for (int o = 16; o; o >>= 1) {
            mn = fminf(mn, __shfl_xor_sync(0xffffffffu, mn, o));
            mx = fmaxf(mx, __shfl_xor_sync(0xffffffffu, mx, o));
        }
        if (tid == 0) s_inv_range = 1.0f / (mx - mn);

        // bar columns: first at 17, stride 3, 32 bars (bar_w=1, gap=2, beg=15)
        char c[4];
        #pragma unroll
        for (int k = 0; k < 4; k++) {
            int w = tid * 4 + k - 17;
            c[k] = (w >= 0 && w <= 93 && (w % 3) == 0) ? (char)(w / 3) : (char)-1;
        }
        sc2b[tid] = make_char4(c[0], c[1], c[2], c[3]);
    }
    __syncthreads();

    const float inv_range = s_inv_range;
    const int   h  = h0 + warp;          // one row per warp
    const int   w4 = lane << 2;

    // ---- fill: pixel-major compute of this lane's 4 pixels (di slot = 0) ----
    const float rc  = sx[h >> 2];
    const float ndv = fabsf(rc - sx[lane]) * inv_range;   // w4>>2 == lane

    const float4 s4 = __ldg((const float4*)(stamp + h * 128 + w4));
    const char4  bb = sc2b[lane];

    const float bar0 = (bb.x >= 0 && h < sbarh[(int)bb.x]) ? 1.0f : 0.0f;
    const float bar1 = (bb.y >= 0 && h < sbarh[(int)bb.y]) ? 1.0f : 0.0f;
    const float bar2 = (bb.z >= 0 && h < sbarh[(int)bb.z]) ? 1.0f : 0.0f;
    const float bar3 = (bb.w >= 0 && h < sbarh[(int)bb.w]) ? 1.0f : 0.0f;

    // 20 floats -> staging (STS.128 @ 80B lane stride: bank conflict-free)
    float4* const stg = stage[warp];
    stg[lane * 5 + 0] = make_float4(s4.x, 0.0f, rc,   ndv);
    stg[lane * 5 + 1] = make_float4(bar0, s4.y, 0.0f, rc);
    stg[lane * 5 + 2] = make_float4(ndv,  bar1, s4.z, 0.0f);
    stg[lane * 5 + 3] = make_float4(rc,   ndv,  bar2, s4.w);
    stg[lane * 5 + 4] = make_float4(0.0f, rc,   ndv,  bar3);
    __syncwarp();

    // ---- scatter patch: <=32 smem atomics into this row's channel-1 slots ----
    // (duplicates at same (r,c) sum via atomicAdd, matching tf.scatter_nd)
    float* const stgF = (float*)stg;
    if (srow[lane] == h)
        atomicAdd(&stgF[scol[lane] * 5 + 1], sx[lane]);
    __syncwarp();

    // ---- drain: single 2560B TMA bulk store, issued by lane 0 ----
    if (lane == 0) {
        uint32_t saddr;
        asm volatile("{ .reg .u64 t; cvta.to.shared.u64 t, %1; cvt.u32.u64 %0, t; }"
                     : "=r"(saddr) : "l"(stg));
        float* gptr = out + (size_t)(b * 128 + h) * 640;   // 128*5 floats/row
        asm volatile("fence.proxy.async.shared::cta;" ::: "memory");
        asm volatile("cp.async.bulk.global.shared::cta.bulk_group [%0], [%1], %2;"
                     :: "l"(gptr), "r"(saddr), "r"(2560u) : "memory");
        asm volatile("cp.async.bulk.commit_group;" ::: "memory");
        asm volatile("cp.async.bulk.wait_group.read 0;" ::: "memory");
    }
}

extern "C" void kernel_launch(void* const* d_in, const int* in_sizes, int n_in,
                              void* d_out, int out_size)
{
    const float* inputs = (const float*)d_in[0];   // [512,32]
    const float* stamp  = (const float*)d_in[1];   // [128,128,1]
    const int*   coords = (const int*)d_in[2];     // [32,2]
    float*       out    = (float*)d_out;           // [512,128,128,5]

    deepinsight_kernel<<<512 * 8, THREADS>>>(inputs, stamp, coords, out);
}

// round 12
// speedup vs baseline: 1.0679x; 1.0679x over previous
#include <cuda_runtime.h>
#include <cstdint>

// DeepInsightEncoding: out[b,h,w,c], c in {stamp, scatter, rowcopy, nd, bars}
// B=512, D=32, H=W=128. Output fp32 [512,128,128,5] = 168 MB -> HBM-write bound.
//
// R12: barrier-free. Every warp is self-sufficient: loads the 32 inputs + its
// coords redundantly, derives scalars via shuffles. Only smem = staging rows.
// Fill (conflict-free STS) -> scatter patch (<=32 smem atomics) -> one 2560B
// TMA bulk store per row.

#define THREADS 512            // 16 warps, one output row per warp
#define NWARPS 16
#define ROWS_PER_CTA 16
#define ROW_F4 160             // 128 px * 5 ch / 4 = 2560 B per row

__global__ void __launch_bounds__(THREADS)
deepinsight_kernel(const float* __restrict__ inputs,   // [512,32]
                   const float* __restrict__ stamp,    // [128,128]
                   const int*   __restrict__ coords,   // [32,2]
                   float*       __restrict__ out)      // [512,128,128,5]
{
    __shared__ __align__(16) float4 stage[NWARPS][ROW_F4]; // 40 KB, only smem

    const int b    = blockIdx.x >> 3;
    const int h0   = (blockIdx.x & 7) * ROWS_PER_CTA;
    const int warp = threadIdx.x >> 5;
    const int lane = threadIdx.x & 31;
    const int h    = h0 + warp;          // this warp's output row

    // ---- per-warp register prologue (no smem, no barriers) ----
    const float v  = __ldg(inputs + b * 32 + lane);       // sx[lane]
    const int2  cd = __ldg((const int2*)coords + lane);   // (row, col) for d=lane

    int bh = (int)rintf(v * 128.0f);                      // round-half-even == jnp.round
    bh = min(max(bh, 0), 128);

    float mn = v, mx = v;
    #pragma unroll
    for (int o = 16; o; o >>= 1) {
        mn = fminf(mn, __shfl_xor_sync(0xffffffffu, mn, o));
        mx = fmaxf(mx, __shfl_xor_sync(0xffffffffu, mx, o));
    }
    const float inv_range = 1.0f / (mx - mn);

    // bar columns: first at 17, stride 3, 32 bars (bar_w=1, gap=2, beg=15)
    int bi[4];
    #pragma unroll
    for (int k = 0; k < 4; k++) {
        int w = lane * 4 + k - 17;
        bi[k] = (w >= 0 && w <= 93 && (w % 3) == 0) ? (w / 3) : -1;
    }

    const float rc  = __shfl_sync(0xffffffffu, v, h >> 2);   // rowcopy value
    const float ndv = fabsf(rc - v) * inv_range;             // nd for cols 4*lane..+3

    float bar[4];
    #pragma unroll
    for (int k = 0; k < 4; k++) {
        int bhk = __shfl_sync(0xffffffffu, bh, bi[k] < 0 ? 0 : bi[k]);
        bar[k] = (bi[k] >= 0 && h < bhk) ? 1.0f : 0.0f;
    }

    const float4 s4 = __ldg((const float4*)(stamp + h * 128 + lane * 4));

    // ---- fill: 20 floats -> staging (STS.128 @ 80B stride: conflict-free) ----
    float4* const stg = stage[warp];
    stg[lane * 5 + 0] = make_float4(s4.x,   0.0f,   rc,     ndv);
    stg[lane * 5 + 1] = make_float4(bar[0], s4.y,   0.0f,   rc);
    stg[lane * 5 + 2] = make_float4(ndv,    bar[1], s4.z,   0.0f);
    stg[lane * 5 + 3] = make_float4(rc,     ndv,    bar[2], s4.w);
    stg[lane * 5 + 4] = make_float4(0.0f,   rc,     ndv,    bar[3]);
    __syncwarp();

    // ---- scatter patch: duplicates sum via atomicAdd (tf.scatter_nd) ----
    float* const stgF = (float*)stg;
    if (cd.x == h)
        atomicAdd(&stgF[cd.y * 5 + 1], v);
    __syncwarp();

    // ---- drain: single 2560B TMA bulk store, issued by lane 0 ----
    if (lane == 0) {
        uint32_t saddr;
        asm volatile("{ .reg .u64 t; cvta.to.shared.u64 t, %1; cvt.u32.u64 %0, t; }"
                     : "=r"(saddr) : "l"(stg));
        float* gptr = out + (size_t)(b * 128 + h) * 640;   // 128*5 floats/row
        asm volatile("fence.proxy.async.shared::cta;" ::: "memory");
        asm volatile("cp.async.bulk.global.shared::cta.bulk_group [%0], [%1], %2;"
                     :: "l"(gptr), "r"(saddr), "r"(2560u) : "memory");
        asm volatile("cp.async.bulk.commit_group;" ::: "memory");
        asm volatile("cp.async.bulk.wait_group.read 0;" ::: "memory");
    }
}

extern "C" void kernel_launch(void* const* d_in, const int* in_sizes, int n_in,
                              void* d_out, int out_size)
{
    const float* inputs = (const float*)d_in[0];   // [512,32]
    const float* stamp  = (const float*)d_in[1];   // [128,128,1]
    const int*   coords = (const int*)d_in[2];     // [32,2]
    float*       out    = (float*)d_out;           // [512,128,128,5]

    deepinsight_kernel<<<512 * 8, THREADS>>>(inputs, stamp, coords, out);
}